// round 12
// baseline (speedup 1.0000x reference)
#include <cuda_runtime.h>
#include <cuda_bf16.h>

// BSplineBasis, uniform knots. Two-region truncated-power form, balancing the
// fma pipe (Horner + 2 knots) against the alu pipe (FSETP/FSEL/FMNMX selects).
//   y = (x - grid[3]) / h in [0,5);  q = (y < 2.5)
//   L: v = P0(y)  + E1 max(y-1,0)^3 + E2 max(y-2,0)^3
//   R: v = P2(z)  + E3 max(z-1,0)^3 + E4 max(z-2,0)^3,  z = y-2
// x: (4096,4096) f32, coefficients: (4096,8) f32, grid: (12,) f32 uniform.

#define S_TOTAL 4096
#define B_TOTAL 4096
#define THREADS 256
#define GRID_X  (S_TOTAL / THREADS)   // 16
#define GRID_Y  128
#define ROWS    (B_TOTAL / GRID_Y)    // 32
#define UN      8                     // rows per buffer (MLP)

__global__ __launch_bounds__(THREADS)
void bspline_kernel(const float* __restrict__ x,
                    const float* __restrict__ coeff,
                    const float* __restrict__ grid,
                    float* __restrict__ out)
{
    const int t = threadIdx.x;
    const int s = blockIdx.x * THREADS + t;

    // ---- Build the two regional tables in registers ----
    const float4* crow = reinterpret_cast<const float4*>(coeff + (size_t)s * 8);
    float4 Aq = crow[0], Bq = crow[1];
    float c8[8] = {Aq.x, Aq.y, Aq.z, Aq.w, Bq.x, Bq.y, Bq.z, Bq.w};

    float pd[5];
    #pragma unroll
    for (int w = 0; w < 5; w++)
        pd[w] = (c8[w+3] - c8[w] + 3.0f * (c8[w+1] - c8[w+2])) * (1.0f / 6.0f);

    // Left region: interval-0 polynomial in y, knots at y=1,2
    const float AL = (c8[0] + 4.0f * c8[1] + c8[2]) * (1.0f / 6.0f);
    const float BL = (c8[2] - c8[0]) * 0.5f;
    const float CL = (c8[0] - 2.0f * c8[1] + c8[2]) * 0.5f;
    const float DL = pd[0];
    const float E1L = pd[1] - pd[0];
    const float E2L = pd[2] - pd[1];
    // Right region: interval-2 polynomial in z = y-2, knots at z=1,2 (y=3,4)
    const float AR = (c8[2] + 4.0f * c8[3] + c8[4]) * (1.0f / 6.0f);
    const float BR = (c8[4] - c8[2]) * 0.5f;
    const float CR = (c8[2] - 2.0f * c8[3] + c8[4]) * 0.5f;
    const float DR = pd[2];
    const float E1R = pd[3] - pd[2];
    const float E2R = pd[4] - pd[3];

    const float gstart = __ldg(&grid[3]);
    const float invh   = 1.0f / (__ldg(&grid[1]) - __ldg(&grid[0]));
    const float c0     = -gstart * invh;                 // y = x*invh + c0

    const int b0 = blockIdx.y * ROWS;
    const float* xp = x   + (size_t)b0 * S_TOTAL + s;
    float*       op = out + (size_t)b0 * S_TOTAL + s;

    float bufA[UN], bufB[UN];

    #pragma unroll
    for (int k = 0; k < UN; k++)
        bufA[k] = xp[(size_t)k * S_TOTAL];

    #pragma unroll 1
    for (int r = 0; r < ROWS; r += 2 * UN) {
        #pragma unroll
        for (int k = 0; k < UN; k++)
            bufB[k] = xp[(size_t)(UN + k) * S_TOTAL];

        #pragma unroll
        for (int k = 0; k < UN; k++) {
            float y  = fmaf(bufA[k], invh, c0);
            bool  q  = y < 2.5f;                    // 1 FSETP
            float z  = q ? y : (y - 2.0f);          // FADD + FSEL
            float a  = q ? AL  : AR;                // 6x FSEL (alu pipe)
            float b  = q ? BL  : BR;
            float c  = q ? CL  : CR;
            float d  = q ? DL  : DR;
            float e1 = q ? E1L : E1R;
            float e2 = q ? E2L : E2R;
            float v  = fmaf(fmaf(fmaf(d, z, c), z, b), z, a);
            float m1 = fmaxf(z - 1.0f, 0.0f);       // FADD + FMNMX(alu)
            float m2 = fmaxf(z - 2.0f, 0.0f);
            v = fmaf(e1, m1 * m1 * m1, v);
            v = fmaf(e2, m2 * m2 * m2, v);
            op[(size_t)k * S_TOTAL] = v;
        }

        if (r + 2 * UN < ROWS) {
            #pragma unroll
            for (int k = 0; k < UN; k++)
                bufA[k] = xp[(size_t)(2 * UN + k) * S_TOTAL];
        }

        #pragma unroll
        for (int k = 0; k < UN; k++) {
            float y  = fmaf(bufB[k], invh, c0);
            bool  q  = y < 2.5f;
            float z  = q ? y : (y - 2.0f);
            float a  = q ? AL  : AR;
            float b  = q ? BL  : BR;
            float c  = q ? CL  : CR;
            float d  = q ? DL  : DR;
            float e1 = q ? E1L : E1R;
            float e2 = q ? E2L : E2R;
            float v  = fmaf(fmaf(fmaf(d, z, c), z, b), z, a);
            float m1 = fmaxf(z - 1.0f, 0.0f);
            float m2 = fmaxf(z - 2.0f, 0.0f);
            v = fmaf(e1, m1 * m1 * m1, v);
            v = fmaf(e2, m2 * m2 * m2, v);
            op[(size_t)(UN + k) * S_TOTAL] = v;
        }

        xp += (size_t)(2 * UN) * S_TOTAL;
        op += (size_t)(2 * UN) * S_TOTAL;
    }
}

extern "C" void kernel_launch(void* const* d_in, const int* in_sizes, int n_in,
                              void* d_out, int out_size)
{
    const float* x     = (const float*)d_in[0];
    const float* coeff = (const float*)d_in[1];
    const float* grid  = (const float*)d_in[2];
    float*       out   = (float*)d_out;

    dim3 g(GRID_X, GRID_Y);   // (16, 128) = 2048 blocks
    bspline_kernel<<<g, THREADS>>>(x, coeff, grid, out);
}